// round 8
// baseline (speedup 1.0000x reference)
#include <cuda_runtime.h>
#include <math.h>
#include <stdint.h>

#define Bq   32
#define Hc   384
#define Tn   1024
#define MAXL 4096
#define NBLK 512               // T/2 winograd blocks per batch
#define NTOT (Bq * NBLK)       // 16384 GEMM columns (m-dim)
#define KT   48                // 384/8 k-chunks
#define MT   (NTOT / 16)       // 1024 m-tiles
#define NT   48                // 384/8 n-tiles (ho)

// ---------------- scratch ----------------
__device__ float g_buf1[(size_t)Bq * Hc * Tn];
__device__ float g_buf2[(size_t)Bq * Hc * Tn];
__device__ float g_M[4][Hc][NTOT];                     // phase GEMM outputs
__device__ float g_Vf[(size_t)4 * KT * MT * 256];      // A frags [p][kt][mt][lane][8] {hi4,lo4}
__device__ float g_Bf[2][4 * KT * NT * 128];           // B frags [conv][p][kt][nt][lane][4] {hx,hy,lx,ly}
__device__ float g_mean[Bq * Tn];
__device__ float g_rstd[Bq * Tn];
__device__ int   g_dur[Bq * Tn];
__device__ int   g_cum[Bq * Tn];

__device__ __forceinline__ uint32_t f2tf32(float x)
{
    uint32_t r;
    asm("cvt.rna.tf32.f32 %0, %1;" : "=r"(r) : "f"(x));
    return r;
}
__device__ __forceinline__ void tf32_split(float x, float& h, float& l)
{
    uint32_t hb = f2tf32(x);
    h = __uint_as_float(hb);
    l = __uint_as_float(f2tf32(x - h));
}

#define MMA_TF32(c, a, b) \
    asm volatile("mma.sync.aligned.m16n8k8.row.col.f32.tf32.tf32.f32 " \
        "{%0,%1,%2,%3}, {%4,%5,%6,%7}, {%8,%9}, {%0,%1,%2,%3};" \
        : "+f"((c)[0]), "+f"((c)[1]), "+f"((c)[2]), "+f"((c)[3]) \
        : "r"(__float_as_uint((a).x)), "r"(__float_as_uint((a).y)), \
          "r"(__float_as_uint((a).z)), "r"(__float_as_uint((a).w)), \
          "r"(__float_as_uint((b).x)), "r"(__float_as_uint((b).y)))

// ---------------- V prep: X -> A fragments; optional fused LN+relu --------------
__global__ void vprep(const float* __restrict__ X, float* __restrict__ Af,
                      int useLN, const float* __restrict__ gam,
                      const float* __restrict__ bet)
{
    int gw = blockIdx.x * 8 + (threadIdx.x >> 5);   // warp per (kt, mt)
    int lane = threadIdx.x & 31;
    int kt = gw >> 10;
    int mt = gw & 1023;
    int g = lane >> 2, t4 = lane & 3;

    float4 outv[4][2];
#pragma unroll
    for (int s = 0; s < 4; s++) {
        int r  = g + ((s & 1) ? 8 : 0);
        int kk = t4 + ((s & 2) ? 4 : 0);
        int m = mt * 16 + r;
        int b = m >> 9, nb = m & 511;
        int hi = kt * 8 + kk;
        const float* xp = X + ((size_t)b * Hc + hi) * Tn;
        int t2 = 2 * nb;
        float gv = 1.f, bv = 0.f;
        if (useLN) { gv = __ldg(gam + hi); bv = __ldg(bet + hi); }
        auto ldv = [&](int tt) -> float {
            if ((unsigned)tt >= (unsigned)Tn) return 0.f;
            float v = __ldg(xp + tt);
            if (useLN) {
                float mn = g_mean[b * Tn + tt];
                float rs = g_rstd[b * Tn + tt];
                v = fmaxf((v - mn) * rs * gv + bv, 0.f);
            }
            return v;
        };
        float d0 = ldv(t2 - 1);
        float d1 = ldv(t2);
        float d2 = ldv(t2 + 1);
        float d3 = ldv(t2 + 2);
        float v[4] = {d0 - d2, d1 + d2, d2 - d1, d1 - d3};
#pragma unroll
        for (int p = 0; p < 4; p++) {
            float h, l;
            tf32_split(v[p], h, l);
            ((float*)&outv[p][0])[s] = h;
            ((float*)&outv[p][1])[s] = l;
        }
    }
#pragma unroll
    for (int p = 0; p < 4; p++) {
        float* dst = Af + (((size_t)p * KT + kt) * MT + mt) * 256 + lane * 8;
        *(float4*)dst       = outv[p][0];   // hi half
        *(float4*)(dst + 4) = outv[p][1];   // lo half
    }
}

// ---------------- B prep: W -> U_p fragments, packed {hx,hy,lx,ly} --------------
__global__ void bprep(const float* __restrict__ W, float* __restrict__ Bf)
{
    int gw = blockIdx.x * 8 + (threadIdx.x >> 5);
    int lane = threadIdx.x & 31;
    int kt = gw / NT, nt = gw % NT;
    int g = lane >> 2, t4 = lane & 3;
    int ho = nt * 8 + g;

    float2 hv[4], lv[4];
#pragma unroll
    for (int s = 0; s < 2; s++) {
        int hi = kt * 8 + t4 + s * 4;
        const float* wp = W + ((size_t)ho * Hc + hi) * 3;
        float g0 = __ldg(wp), g1 = __ldg(wp + 1), g2 = __ldg(wp + 2);
        float u[4] = {g0, 0.5f * (g0 + g1 + g2), 0.5f * (g0 - g1 + g2), g2};
#pragma unroll
        for (int p = 0; p < 4; p++) {
            float h, l;
            tf32_split(u[p], h, l);
            ((float*)&hv[p])[s] = h;
            ((float*)&lv[p])[s] = l;
        }
    }
#pragma unroll
    for (int p = 0; p < 4; p++) {
        float* dst = Bf + (((size_t)p * KT + kt) * NT + nt) * 128 + lane * 4;
        *(float4*)dst = make_float4(hv[p].x, hv[p].y, lv[p].x, lv[p].y);
    }
}

// ---------------- phase GEMM: A depth-2 prefetch (3 bufs), B depth-1 (2 bufs) ----
__global__ __launch_bounds__(256, 1)
void wino_mma(const float* __restrict__ Af, const float* __restrict__ Bf,
              float* __restrict__ M)
{
    const int p = blockIdx.z, mc = blockIdx.x, nc = blockIdx.y;
    const int w = threadIdx.x >> 5, lane = threadIdx.x & 31;
    const int wm = w & 3, wn = w >> 2;
    const int mt0 = mc * 8 + wm * 2;
    const int nt0 = nc * 16 + wn * 8;

    float c[16][4];
#pragma unroll
    for (int i = 0; i < 16; i++)
#pragma unroll
        for (int r = 0; r < 4; r++) c[i][r] = 0.f;

    const float* Ap = Af + ((size_t)p * KT * MT) * 256 + (size_t)mt0 * 256 + lane * 8;
    const float* Bp = Bf + ((size_t)p * KT * NT) * 128 + (size_t)nt0 * 128 + lane * 4;

    float4 a[3][2][2];   // [buf][tile][half] — DRAM operand, depth-2
    float4 bb[2][8];     // [buf][tile]       — L2 operand, depth-1

    auto loadA = [&](int kt, int bi) {
        const float* ak = Ap + (size_t)kt * MT * 256;
#pragma unroll
        for (int i = 0; i < 2; i++) {
            a[bi][i][0] = __ldg((const float4*)(ak + (size_t)i * 256));
            a[bi][i][1] = __ldg((const float4*)(ak + (size_t)i * 256 + 4));
        }
    };
    auto loadB = [&](int kt, int bi) {
        const float* bk = Bp + (size_t)kt * NT * 128;
#pragma unroll
        for (int j = 0; j < 8; j++)
            bb[bi][j] = __ldg((const float4*)(bk + (size_t)j * 128));
    };

    loadA(0, 0);
    loadA(1, 1);
    loadB(0, 0);
#pragma unroll 3
    for (int kt = 0; kt < KT; kt++) {
        const int ca = kt % 3;
        const int cb = kt & 1;
        if (kt + 2 < KT) loadA(kt + 2, (kt + 2) % 3);
        if (kt + 1 < KT) loadB(kt + 1, cb ^ 1);
#pragma unroll
        for (int i = 0; i < 2; i++)
#pragma unroll
            for (int j = 0; j < 8; j++) {
                float2 bh = make_float2(bb[cb][j].x, bb[cb][j].y);
                float2 bl = make_float2(bb[cb][j].z, bb[cb][j].w);
                MMA_TF32(c[i * 8 + j], a[ca][i][0], bh);
                MMA_TF32(c[i * 8 + j], a[ca][i][0], bl);
                MMA_TF32(c[i * 8 + j], a[ca][i][1], bh);
            }
    }

    const int g = lane >> 2, t4 = lane & 3;
#pragma unroll
    for (int i = 0; i < 2; i++)
#pragma unroll
        for (int j = 0; j < 8; j++) {
            int m  = mc * 128 + wm * 32 + i * 16 + g;
            int ho = nc * 128 + wn * 64 + j * 8 + 2 * t4;
            float* mp = M + ((size_t)p * Hc + ho) * NTOT + m;
            mp[0]        = c[i * 8 + j][0];
            mp[NTOT]     = c[i * 8 + j][1];
            mp[8]        = c[i * 8 + j][2];
            mp[NTOT + 8] = c[i * 8 + j][3];
        }
}

// ---------------- output transform (fully parallel, coalesced) ----------------
__global__ void wino_out(const float* __restrict__ M, const float* __restrict__ bias,
                         float* __restrict__ Y)
{
    int i = blockIdx.x * 256 + threadIdx.x;
    int nb = i & (NBLK - 1);
    int tmp = i >> 9;
    int ho = tmp % Hc;
    int b = tmp / Hc;
    size_t col = (size_t)b * NBLK + nb;
    const float* mp = M + (size_t)ho * NTOT + col;
    float m1 = mp[0];
    float m2 = mp[(size_t)Hc * NTOT];
    float m3 = mp[2 * (size_t)Hc * NTOT];
    float m4 = mp[3 * (size_t)Hc * NTOT];
    float bi = __ldg(bias + ho);
    float2 y = make_float2(m1 + m2 + m3 + bi, m2 - m3 - m4 + bi);
    *(float2*)(Y + ((size_t)b * Hc + ho) * Tn + 2 * nb) = y;
}

// ---------------- LN stats over channel dim ----------------
__global__ void ln_stats(const float* __restrict__ Y)
{
    int b = blockIdx.y;
    int t = blockIdx.x * 256 + threadIdx.x;
    const float* p = Y + (size_t)b * Hc * Tn + t;
    float s = 0.f, s2 = 0.f;
#pragma unroll 8
    for (int h = 0; h < Hc; h++) {
        float v = __ldg(p + (size_t)h * Tn);
        s += v; s2 += v * v;
    }
    float m = s * (1.f / Hc);
    float var = s2 * (1.f / Hc) - m * m;
    g_mean[b * Tn + t] = m;
    g_rstd[b * Tn + t] = rsqrtf(var + 1e-5f);
}

// ---------------- LN2 + relu + dot(Wl) + duration ----------------
__global__ void ln_dot_dur(const float* __restrict__ Y2,
                           const float* __restrict__ g, const float* __restrict__ be,
                           const float* __restrict__ Wl, const float* __restrict__ bl,
                           float* __restrict__ durF)
{
    int b = blockIdx.y;
    int t = blockIdx.x * 256 + threadIdx.x;
    const float* p = Y2 + (size_t)b * Hc * Tn + t;
    float m = g_mean[b * Tn + t];
    float r = g_rstd[b * Tn + t];
    float acc = 0.f;
#pragma unroll 8
    for (int h = 0; h < Hc; h++) {
        float v = (__ldg(p + (size_t)h * Tn) - m) * r * __ldg(g + h) + __ldg(be + h);
        acc += fmaxf(v, 0.f) * __ldg(Wl + h);
    }
    float z = fmaxf(acc + __ldg(bl), 0.f);
    int d = (int)floorf(expf(z));
    g_dur[b * Tn + t] = d;
    durF[b * Tn + t] = (float)d;
}

__global__ void cumsum_k()
{
    __shared__ int s[Tn];
    int b = blockIdx.x, t = threadIdx.x;
    s[t] = g_dur[b * Tn + t];
    __syncthreads();
#pragma unroll
    for (int off = 1; off < Tn; off <<= 1) {
        int v = (t >= off) ? s[t - off] : 0;
        __syncthreads();
        s[t] += v;
        __syncthreads();
    }
    g_cum[b * Tn + t] = s[t];
}

__global__ void gather_k(const float* __restrict__ X, float* __restrict__ outAligned)
{
    __shared__ int sc[Tn];
    int b = blockIdx.y;
    int tid = threadIdx.x;
#pragma unroll
    for (int e = 0; e < 4; e++) sc[tid + 256 * e] = g_cum[b * Tn + tid + 256 * e];
    __syncthreads();

    int pos = blockIdx.x * 256 + tid;
    int total = sc[Tn - 1];
    bool valid = pos < total;
    int lo = 0, hi = Tn;
    while (lo < hi) {
        int mid = (lo + hi) >> 1;
        if (sc[mid] <= pos) lo = mid + 1; else hi = mid;
    }
    int idx = min(lo, Tn - 1);

    const float* xb = X + (size_t)b * Hc * Tn;
    float* ob = outAligned + (size_t)b * Hc * MAXL + pos;
    if (valid) {
#pragma unroll 4
        for (int h = 0; h < Hc; h++) ob[(size_t)h * MAXL] = __ldg(xb + (size_t)h * Tn + idx);
    } else {
#pragma unroll 4
        for (int h = 0; h < Hc; h++) ob[(size_t)h * MAXL] = 0.f;
    }
}

// ---------------------------------------------------------------------------------
extern "C" void kernel_launch(void* const* d_in, const int* in_sizes, int n_in,
                              void* d_out, int out_size)
{
    const float* x  = (const float*)d_in[0];
    const float* W1 = (const float*)d_in[1];
    const float* b1 = (const float*)d_in[2];
    const float* g1 = (const float*)d_in[3];
    const float* be1= (const float*)d_in[4];
    const float* W2 = (const float*)d_in[5];
    const float* b2 = (const float*)d_in[6];
    const float* g2 = (const float*)d_in[7];
    const float* be2= (const float*)d_in[8];
    const float* Wl = (const float*)d_in[9];
    const float* bl = (const float*)d_in[10];

    float* out = (float*)d_out;
    float* outDur     = out;
    float* outAligned = out + Bq * Tn;

    float *buf1, *buf2, *Mbuf, *Vf, *Bf;
    cudaGetSymbolAddress((void**)&buf1, g_buf1);
    cudaGetSymbolAddress((void**)&buf2, g_buf2);
    cudaGetSymbolAddress((void**)&Mbuf, g_M);
    cudaGetSymbolAddress((void**)&Vf, g_Vf);
    cudaGetSymbolAddress((void**)&Bf, g_Bf);
    float* Bf1 = Bf;
    float* Bf2 = Bf + 4 * KT * NT * 128;

    dim3 mma_grid(NTOT / 128, Hc / 128, 4);
    dim3 ln_grid(Tn / 256, Bq);

    bprep<<<(KT * NT) / 8, 256>>>(W1, Bf1);
    bprep<<<(KT * NT) / 8, 256>>>(W2, Bf2);

    // conv1
    vprep<<<(KT * MT) / 8, 256>>>(x, Vf, 0, g1, be1);
    wino_mma<<<mma_grid, 256>>>(Vf, Bf1, Mbuf);
    wino_out<<<(Bq * Hc * NBLK) / 256, 256>>>(Mbuf, b1, buf1);
    ln_stats<<<ln_grid, 256>>>(buf1);
    // conv2 (LN1 + relu fused into vprep)
    vprep<<<(KT * MT) / 8, 256>>>(buf1, Vf, 1, g1, be1);
    wino_mma<<<mma_grid, 256>>>(Vf, Bf2, Mbuf);
    wino_out<<<(Bq * Hc * NBLK) / 256, 256>>>(Mbuf, b2, buf2);
    ln_stats<<<ln_grid, 256>>>(buf2);
    // LN2 + relu + dot + durations
    ln_dot_dur<<<ln_grid, 256>>>(buf2, g2, be2, Wl, bl, outDur);

    cumsum_k<<<Bq, Tn>>>();
    gather_k<<<dim3(MAXL / 256, Bq), 256>>>(x, outAligned);
}

// round 9
// speedup vs baseline: 1.5073x; 1.5073x over previous
#include <cuda_runtime.h>
#include <math.h>
#include <stdint.h>

#define Bq   32
#define Hc   384
#define Tn   1024
#define MAXL 4096
#define NBLK 512               // T/2 winograd blocks per batch
#define NTOT (Bq * NBLK)       // 16384 GEMM columns (m-dim)
#define KT   48                // 384/8 k-chunks
#define MT   (NTOT / 16)       // 1024 m-tiles
#define NT   48                // 384/8 n-tiles (ho)

// ---------------- scratch ----------------
__device__ float g_buf1[(size_t)Bq * Hc * Tn];
__device__ float g_buf2[(size_t)Bq * Hc * Tn];
__device__ float g_M[4][Hc][NTOT];                       // phase GEMM outputs
__device__ float g_Vf[(size_t)4 * 2 * KT * MT * 128];    // A frags [p][h][kt][mt][lane][4]
__device__ float g_Bf[2][4 * 2 * KT * NT * 64];          // B frags [conv][p][h][kt][nt][lane][2]
__device__ float g_mean[Bq * Tn];
__device__ float g_rstd[Bq * Tn];
__device__ int   g_dur[Bq * Tn];
__device__ int   g_cum[Bq * Tn];

__device__ __forceinline__ uint32_t f2tf32(float x)
{
    uint32_t r;
    asm("cvt.rna.tf32.f32 %0, %1;" : "=r"(r) : "f"(x));
    return r;
}
__device__ __forceinline__ void tf32_split(float x, float& h, float& l)
{
    uint32_t hb = f2tf32(x);
    h = __uint_as_float(hb);
    l = __uint_as_float(f2tf32(x - h));
}

#define MMA_TF32(c, a, b) \
    asm volatile("mma.sync.aligned.m16n8k8.row.col.f32.tf32.tf32.f32 " \
        "{%0,%1,%2,%3}, {%4,%5,%6,%7}, {%8,%9}, {%0,%1,%2,%3};" \
        : "+f"((c)[0]), "+f"((c)[1]), "+f"((c)[2]), "+f"((c)[3]) \
        : "r"(__float_as_uint((a).x)), "r"(__float_as_uint((a).y)), \
          "r"(__float_as_uint((a).z)), "r"(__float_as_uint((a).w)), \
          "r"(__float_as_uint((b).x)), "r"(__float_as_uint((b).y)))

// ---------------- V prep: X -> A fragments; optional fused LN+relu --------------
__global__ void vprep(const float* __restrict__ X, float* __restrict__ Af,
                      int useLN, const float* __restrict__ gam,
                      const float* __restrict__ bet)
{
    int gw = blockIdx.x * 8 + (threadIdx.x >> 5);   // warp per (kt, mt)
    int lane = threadIdx.x & 31;
    int kt = gw >> 10;
    int mt = gw & 1023;
    int g = lane >> 2, t4 = lane & 3;

    float4 outv[4][2];
#pragma unroll
    for (int s = 0; s < 4; s++) {
        int r  = g + ((s & 1) ? 8 : 0);
        int kk = t4 + ((s & 2) ? 4 : 0);
        int m = mt * 16 + r;
        int b = m >> 9, nb = m & 511;
        int hi = kt * 8 + kk;
        const float* xp = X + ((size_t)b * Hc + hi) * Tn;
        int t2 = 2 * nb;
        float gv = 1.f, bv = 0.f;
        if (useLN) { gv = __ldg(gam + hi); bv = __ldg(bet + hi); }
        auto ldv = [&](int tt) -> float {
            if ((unsigned)tt >= (unsigned)Tn) return 0.f;
            float v = __ldg(xp + tt);
            if (useLN) {
                float mn = g_mean[b * Tn + tt];
                float rs = g_rstd[b * Tn + tt];
                v = fmaxf((v - mn) * rs * gv + bv, 0.f);
            }
            return v;
        };
        float d0 = ldv(t2 - 1);
        float d1 = ldv(t2);
        float d2 = ldv(t2 + 1);
        float d3 = ldv(t2 + 2);
        float v[4] = {d0 - d2, d1 + d2, d2 - d1, d1 - d3};
#pragma unroll
        for (int p = 0; p < 4; p++) {
            float h, l;
            tf32_split(v[p], h, l);
            ((float*)&outv[p][0])[s] = h;
            ((float*)&outv[p][1])[s] = l;
        }
    }
#pragma unroll
    for (int p = 0; p < 4; p++)
#pragma unroll
        for (int h = 0; h < 2; h++)
            *(float4*)(Af + ((((size_t)(p * 2 + h) * KT + kt) * MT + mt) * 128) + lane * 4)
                = outv[p][h];
}

// ---------------- B prep: W -> U_p fragments ----------------
__global__ void bprep(const float* __restrict__ W, float* __restrict__ Bf)
{
    int gw = blockIdx.x * 8 + (threadIdx.x >> 5);
    int lane = threadIdx.x & 31;
    int kt = gw / NT, nt = gw % NT;
    int g = lane >> 2, t4 = lane & 3;
    int ho = nt * 8 + g;

    float2 outv[4][2];
#pragma unroll
    for (int s = 0; s < 2; s++) {
        int hi = kt * 8 + t4 + s * 4;
        const float* wp = W + ((size_t)ho * Hc + hi) * 3;
        float g0 = __ldg(wp), g1 = __ldg(wp + 1), g2 = __ldg(wp + 2);
        float u[4] = {g0, 0.5f * (g0 + g1 + g2), 0.5f * (g0 - g1 + g2), g2};
#pragma unroll
        for (int p = 0; p < 4; p++) {
            float h, l;
            tf32_split(u[p], h, l);
            ((float*)&outv[p][0])[s] = h;
            ((float*)&outv[p][1])[s] = l;
        }
    }
#pragma unroll
    for (int p = 0; p < 4; p++)
#pragma unroll
        for (int h = 0; h < 2; h++)
            *(float2*)(Bf + ((((size_t)(p * 2 + h) * KT + kt) * NT + nt) * 64) + lane * 2)
                = outv[p][h];
}

// ---------------- phase GEMM: 32m x 32n warp tile, 2 CTAs/SM ----------------
// 8 warps as 4(m) x 2(n); CTA tile 128(m) x 64(n); double-buffered frag loads.
__global__ __launch_bounds__(256, 2)
void wino_mma(const float* __restrict__ Af, const float* __restrict__ Bf,
              float* __restrict__ M)
{
    const int p = blockIdx.z, mc = blockIdx.x, nc = blockIdx.y;
    const int w = threadIdx.x >> 5, lane = threadIdx.x & 31;
    const int wm = w & 3, wn = w >> 2;
    const int mt0 = mc * 8 + wm * 2;
    const int nt0 = nc * 8 + wn * 4;

    float c[8][4];
#pragma unroll
    for (int i = 0; i < 8; i++)
#pragma unroll
        for (int r = 0; r < 4; r++) c[i][r] = 0.f;

    const float* A0 = Af + (size_t)(p * 2 + 0) * KT * MT * 128 + (size_t)mt0 * 128 + lane * 4;
    const float* A1 = Af + (size_t)(p * 2 + 1) * KT * MT * 128 + (size_t)mt0 * 128 + lane * 4;
    const float* B0 = Bf + (size_t)(p * 2 + 0) * KT * NT * 64 + (size_t)nt0 * 64 + lane * 2;
    const float* B1 = Bf + (size_t)(p * 2 + 1) * KT * NT * 64 + (size_t)nt0 * 64 + lane * 2;

    float4 a[2][2][2];   // [buf][tile][half]
    float2 b[2][4][2];   // [buf][tile][half]

    auto loadf = [&](int kt, int bi) {
        const size_t ao = (size_t)kt * MT * 128;
        const size_t bo = (size_t)kt * NT * 64;
#pragma unroll
        for (int i = 0; i < 2; i++) {
            a[bi][i][0] = __ldg((const float4*)(A0 + ao + (size_t)i * 128));
            a[bi][i][1] = __ldg((const float4*)(A1 + ao + (size_t)i * 128));
        }
#pragma unroll
        for (int j = 0; j < 4; j++) {
            b[bi][j][0] = __ldg((const float2*)(B0 + bo + (size_t)j * 64));
            b[bi][j][1] = __ldg((const float2*)(B1 + bo + (size_t)j * 64));
        }
    };

    loadf(0, 0);
#pragma unroll 2
    for (int kt = 0; kt < KT; kt++) {
        const int cur = kt & 1;
        if (kt + 1 < KT) loadf(kt + 1, cur ^ 1);
#pragma unroll
        for (int i = 0; i < 2; i++)
#pragma unroll
            for (int j = 0; j < 4; j++) {
                MMA_TF32(c[i * 4 + j], a[cur][i][0], b[cur][j][0]);
                MMA_TF32(c[i * 4 + j], a[cur][i][0], b[cur][j][1]);
                MMA_TF32(c[i * 4 + j], a[cur][i][1], b[cur][j][0]);
            }
    }

    const int g = lane >> 2, t4 = lane & 3;
#pragma unroll
    for (int i = 0; i < 2; i++)
#pragma unroll
        for (int j = 0; j < 4; j++) {
            int m  = mc * 128 + wm * 32 + i * 16 + g;
            int ho = nc * 64 + wn * 32 + j * 8 + 2 * t4;
            float* mp = M + ((size_t)p * Hc + ho) * NTOT + m;
            mp[0]        = c[i * 4 + j][0];
            mp[NTOT]     = c[i * 4 + j][1];
            mp[8]        = c[i * 4 + j][2];
            mp[NTOT + 8] = c[i * 4 + j][3];
        }
}

// ---------------- output transform (fully parallel, coalesced) ----------------
__global__ void wino_out(const float* __restrict__ M, const float* __restrict__ bias,
                         float* __restrict__ Y)
{
    int i = blockIdx.x * 256 + threadIdx.x;
    int nb = i & (NBLK - 1);
    int tmp = i >> 9;
    int ho = tmp % Hc;
    int b = tmp / Hc;
    size_t col = (size_t)b * NBLK + nb;
    const float* mp = M + (size_t)ho * NTOT + col;
    float m1 = mp[0];
    float m2 = mp[(size_t)Hc * NTOT];
    float m3 = mp[2 * (size_t)Hc * NTOT];
    float m4 = mp[3 * (size_t)Hc * NTOT];
    float bi = __ldg(bias + ho);
    float2 y = make_float2(m1 + m2 + m3 + bi, m2 - m3 - m4 + bi);
    *(float2*)(Y + ((size_t)b * Hc + ho) * Tn + 2 * nb) = y;
}

// ---------------- LN stats over channel dim ----------------
__global__ void ln_stats(const float* __restrict__ Y)
{
    int b = blockIdx.y;
    int t = blockIdx.x * 256 + threadIdx.x;
    const float* p = Y + (size_t)b * Hc * Tn + t;
    float s = 0.f, s2 = 0.f;
#pragma unroll 8
    for (int h = 0; h < Hc; h++) {
        float v = __ldg(p + (size_t)h * Tn);
        s += v; s2 += v * v;
    }
    float m = s * (1.f / Hc);
    float var = s2 * (1.f / Hc) - m * m;
    g_mean[b * Tn + t] = m;
    g_rstd[b * Tn + t] = rsqrtf(var + 1e-5f);
}

// ---------------- LN2 + relu + dot(Wl) + duration ----------------
__global__ void ln_dot_dur(const float* __restrict__ Y2,
                           const float* __restrict__ g, const float* __restrict__ be,
                           const float* __restrict__ Wl, const float* __restrict__ bl,
                           float* __restrict__ durF)
{
    int b = blockIdx.y;
    int t = blockIdx.x * 256 + threadIdx.x;
    const float* p = Y2 + (size_t)b * Hc * Tn + t;
    float m = g_mean[b * Tn + t];
    float r = g_rstd[b * Tn + t];
    float acc = 0.f;
#pragma unroll 8
    for (int h = 0; h < Hc; h++) {
        float v = (__ldg(p + (size_t)h * Tn) - m) * r * __ldg(g + h) + __ldg(be + h);
        acc += fmaxf(v, 0.f) * __ldg(Wl + h);
    }
    float z = fmaxf(acc + __ldg(bl), 0.f);
    int d = (int)floorf(expf(z));
    g_dur[b * Tn + t] = d;
    durF[b * Tn + t] = (float)d;
}

__global__ void cumsum_k()
{
    __shared__ int s[Tn];
    int b = blockIdx.x, t = threadIdx.x;
    s[t] = g_dur[b * Tn + t];
    __syncthreads();
#pragma unroll
    for (int off = 1; off < Tn; off <<= 1) {
        int v = (t >= off) ? s[t - off] : 0;
        __syncthreads();
        s[t] += v;
        __syncthreads();
    }
    g_cum[b * Tn + t] = s[t];
}

__global__ void gather_k(const float* __restrict__ X, float* __restrict__ outAligned)
{
    __shared__ int sc[Tn];
    int b = blockIdx.y;
    int tid = threadIdx.x;
#pragma unroll
    for (int e = 0; e < 4; e++) sc[tid + 256 * e] = g_cum[b * Tn + tid + 256 * e];
    __syncthreads();

    int pos = blockIdx.x * 256 + tid;
    int total = sc[Tn - 1];
    bool valid = pos < total;
    int lo = 0, hi = Tn;
    while (lo < hi) {
        int mid = (lo + hi) >> 1;
        if (sc[mid] <= pos) lo = mid + 1; else hi = mid;
    }
    int idx = min(lo, Tn - 1);

    const float* xb = X + (size_t)b * Hc * Tn;
    float* ob = outAligned + (size_t)b * Hc * MAXL + pos;
    if (valid) {
#pragma unroll 4
        for (int h = 0; h < Hc; h++) ob[(size_t)h * MAXL] = __ldg(xb + (size_t)h * Tn + idx);
    } else {
#pragma unroll 4
        for (int h = 0; h < Hc; h++) ob[(size_t)h * MAXL] = 0.f;
    }
}

// ---------------------------------------------------------------------------------
extern "C" void kernel_launch(void* const* d_in, const int* in_sizes, int n_in,
                              void* d_out, int out_size)
{
    const float* x  = (const float*)d_in[0];
    const float* W1 = (const float*)d_in[1];
    const float* b1 = (const float*)d_in[2];
    const float* g1 = (const float*)d_in[3];
    const float* be1= (const float*)d_in[4];
    const float* W2 = (const float*)d_in[5];
    const float* b2 = (const float*)d_in[6];
    const float* g2 = (const float*)d_in[7];
    const float* be2= (const float*)d_in[8];
    const float* Wl = (const float*)d_in[9];
    const float* bl = (const float*)d_in[10];

    float* out = (float*)d_out;
    float* outDur     = out;
    float* outAligned = out + Bq * Tn;

    float *buf1, *buf2, *Mbuf, *Vf, *Bf;
    cudaGetSymbolAddress((void**)&buf1, g_buf1);
    cudaGetSymbolAddress((void**)&buf2, g_buf2);
    cudaGetSymbolAddress((void**)&Mbuf, g_M);
    cudaGetSymbolAddress((void**)&Vf, g_Vf);
    cudaGetSymbolAddress((void**)&Bf, g_Bf);
    float* Bf1 = Bf;
    float* Bf2 = Bf + 4 * 2 * KT * NT * 64;

    dim3 mma_grid(NTOT / 128, Hc / 64, 4);   // (128, 6, 4)
    dim3 ln_grid(Tn / 256, Bq);

    bprep<<<(KT * NT) / 8, 256>>>(W1, Bf1);
    bprep<<<(KT * NT) / 8, 256>>>(W2, Bf2);

    // conv1
    vprep<<<(KT * MT) / 8, 256>>>(x, Vf, 0, g1, be1);
    wino_mma<<<mma_grid, 256>>>(Vf, Bf1, Mbuf);
    wino_out<<<(Bq * Hc * NBLK) / 256, 256>>>(Mbuf, b1, buf1);
    ln_stats<<<ln_grid, 256>>>(buf1);
    // conv2 (LN1 + relu fused into vprep)
    vprep<<<(KT * MT) / 8, 256>>>(buf1, Vf, 1, g1, be1);
    wino_mma<<<mma_grid, 256>>>(Vf, Bf2, Mbuf);
    wino_out<<<(Bq * Hc * NBLK) / 256, 256>>>(Mbuf, b2, buf2);
    ln_stats<<<ln_grid, 256>>>(buf2);
    // LN2 + relu + dot + durations
    ln_dot_dur<<<ln_grid, 256>>>(buf2, g2, be2, Wl, bl, outDur);

    cumsum_k<<<Bq, Tn>>>();
    gather_k<<<dim3(MAXL / 256, Bq), 256>>>(x, outAligned);
}